// round 3
// baseline (speedup 1.0000x reference)
#include <cuda_runtime.h>

#define EPSF 1e-5f

// Problem dims
#define NN  64
#define CC  64
#define TD  300
#define VV  25
#define SS  3
#define ICn 16
#define OCn 64

// Kernel A tiling
#define TTA    10             // t's per subtile
#define SUBS   10             // subtiles per block
#define TCHUNK (TTA*SUBS)     // 100 t's per block
#define NCH    3              // TD / TCHUNK
#define COLA   (TTA*VV)       // 250 flattened cols per subtile
#define ABS_R  28             // padded row stride for s_a/s_b
#define KROWS  (ICn*TTA)      // 160

// Kernel B tiling
#define TTB  5
#define COLB (TTB*VV)         // 125
#define XMS  132              // padded xm row stride (16B aligned)
#define NTB  (TD/TTB)         // 60
#define XROW 28               // padded per-(c,lt) x row

typedef unsigned long long u64;

__device__ float g_Mpart[NCH*NN*SS*VV*VV];
__device__ float g_Aadp [NN*SS*VV*VV];

__device__ __forceinline__ float tanh_fast(float x) {
    float y;
    asm("tanh.approx.f32 %0, %1;" : "=f"(y) : "f"(x));
    return y;
}
__device__ __forceinline__ u64 pack2(float lo, float hi) {
    u64 r; asm("mov.b64 %0, {%1, %2};" : "=l"(r) : "f"(lo), "f"(hi)); return r;
}
__device__ __forceinline__ float2 unpack2(u64 p) {
    float2 r; asm("mov.b64 {%0, %1}, %2;" : "=f"(r.x), "=f"(r.y) : "l"(p)); return r;
}
__device__ __forceinline__ void fma2(u64& d, u64 a, u64 b) {
    asm("fma.rn.f32x2 %0, %1, %2, %0;" : "+l"(d) : "l"(a), "l"(b));
}

// ---------------------------------------------------------------------------
// Kernel A: per (chunk, s, n): a = tanh(bn(Wa x)), b = tanh(bn(Wb x)),
// partial M[v,w] += a^T b over 100 t's. Thread = flattened col; x via LDG.
// ---------------------------------------------------------------------------
__global__ __launch_bounds__(256, 2) void kA(
    const float* __restrict__ x,
    const float* __restrict__ wa, const float* __restrict__ ba,
    const float* __restrict__ wb, const float* __restrict__ bb,
    const float* __restrict__ gag, const float* __restrict__ gab,
    const float* __restrict__ gam, const float* __restrict__ gav,
    const float* __restrict__ gbg, const float* __restrict__ gbb,
    const float* __restrict__ gbm, const float* __restrict__ gbv)
{
    __shared__ __align__(16) float s_w[CC*32];   // [c][0..15]=wa', [16..31]=wb'
    __shared__ float s_sha[ICn], s_shb[ICn];
    __shared__ __align__(16) float s_a[KROWS*ABS_R + 8];
    __shared__ __align__(16) float s_b[KROWS*ABS_R + 8];

    const int tid  = threadIdx.x;
    const int wid  = tid >> 5;
    const int lane = tid & 31;
    const int chunk = blockIdx.x;
    const int s     = blockIdx.y;
    const int n     = blockIdx.z;

    // Fold BN into weights
    for (int idx = tid; idx < ICn*CC; idx += 256) {
        int i = idx / CC, c = idx % CC;
        float sca = gag[s*ICn+i] * rsqrtf(gav[s*ICn+i] + EPSF);
        float scb = gbg[s*ICn+i] * rsqrtf(gbv[s*ICn+i] + EPSF);
        s_w[c*32 + i]      = wa[s*ICn*CC + idx] * sca;
        s_w[c*32 + 16 + i] = wb[s*ICn*CC + idx] * scb;
    }
    if (tid < ICn) {
        float sca = gag[s*ICn+tid] * rsqrtf(gav[s*ICn+tid] + EPSF);
        float scb = gbg[s*ICn+tid] * rsqrtf(gbv[s*ICn+tid] + EPSF);
        s_sha[tid] = (ba[s*ICn+tid] - gam[s*ICn+tid]) * sca + gab[s*ICn+tid];
        s_shb[tid] = (bb[s*ICn+tid] - gbm[s*ICn+tid]) * scb + gbb[s*ICn+tid];
    }

    const int col = tid;            // flattened (t,v) within subtile
    const int lt  = col / 25;
    const int v   = col - lt*25;
    const bool act = (col < COLA);

    // Persistent M accumulators: lane = v, w pairs (wid*4, wid*4+1), (+2,+3)
    u64 maccP[2] = {0ull, 0ull};

    const float* xbase = x + (size_t)n*(CC*TD*VV) + (size_t)(chunk*TCHUNK)*VV;

    for (int sub = 0; sub < SUBS; sub++) {
        __syncthreads();   // prior M-acc reads finished before overwrite
        if (act) {
            u64 acc[16];   // [0..7]=a i-pairs, [8..15]=b i-pairs
            #pragma unroll
            for (int j = 0; j < 8; j++) {
                acc[j]   = pack2(s_sha[2*j], s_sha[2*j+1]);
                acc[8+j] = pack2(s_shb[2*j], s_shb[2*j+1]);
            }
            const float* xp = xbase + sub*COLA + col;
            #pragma unroll 4
            for (int c = 0; c < CC; c++) {
                float xv = __ldg(xp + (size_t)c*(TD*VV));
                u64 x2 = pack2(xv, xv);
                const ulonglong2* wrow =
                    reinterpret_cast<const ulonglong2*>(&s_w[c*32]);
                #pragma unroll
                for (int g = 0; g < 8; g++) {
                    ulonglong2 w2 = wrow[g];
                    fma2(acc[2*g],   w2.x, x2);
                    fma2(acc[2*g+1], w2.y, x2);
                }
            }
            #pragma unroll
            for (int j = 0; j < 8; j++) {
                float2 fa = unpack2(acc[j]);
                float2 fb = unpack2(acc[8+j]);
                s_a[((2*j)*TTA   + lt)*ABS_R + v] = tanh_fast(fa.x);
                s_a[((2*j+1)*TTA + lt)*ABS_R + v] = tanh_fast(fa.y);
                s_b[((2*j)*TTA   + lt)*ABS_R + v] = tanh_fast(fb.x);
                s_b[((2*j+1)*TTA + lt)*ABS_R + v] = tanh_fast(fb.y);
            }
        }
        __syncthreads();

        // M accumulate over K = 160 rows
        #pragma unroll 4
        for (int kk = 0; kk < KROWS; kk++) {
            float av = s_a[kk*ABS_R + lane];
            u64 avp = pack2(av, av);
            ulonglong2 bv = *reinterpret_cast<const ulonglong2*>(
                &s_b[kk*ABS_R + wid*4]);
            fma2(maccP[0], avp, bv.x);
            fma2(maccP[1], avp, bv.y);
        }
    }

    if (lane < VV) {
        float* mp = &g_Mpart[((size_t)chunk*NN*SS + (size_t)n*SS + s)*(VV*VV)];
        float2 m0 = unpack2(maccP[0]);
        float2 m1 = unpack2(maccP[1]);
        int w = wid*4;
        if (w   < VV) mp[lane*VV + w]   = m0.x;
        if (w+1 < VV) mp[lane*VV + w+1] = m0.y;
        if (w+2 < VV) mp[lane*VV + w+2] = m1.x;
        if (w+3 < VV) mp[lane*VV + w+3] = m1.y;
    }
}

// ---------------------------------------------------------------------------
// Kernel A2: reduce partials, A_adp = A + tanh(M/(IC*T)) * alpha
// ---------------------------------------------------------------------------
__global__ void kA2(const float* __restrict__ A, const float* __restrict__ alpha)
{
    int idx = blockIdx.x * 256 + threadIdx.x;
    if (idx >= NN*SS*VV*VV) return;
    float m = 0.f;
    #pragma unroll
    for (int ch = 0; ch < NCH; ch++)
        m += g_Mpart[ch*(NN*SS*VV*VV) + idx];
    g_Aadp[idx] = A[idx % (SS*VV*VV)]
                + tanhf(m * (1.f/(float)(ICn*TD))) * alpha[0];
}

// ---------------------------------------------------------------------------
// Kernel B: per (t-tile, n): for each s: xm = x_tile @ A_adp (K=25),
// y += WdT @ xm (K=64). f32x2 packed. Epilogue: BN + residual + ReLU.
// ---------------------------------------------------------------------------
__global__ __launch_bounds__(256) void kB(
    const float* __restrict__ x,
    const float* __restrict__ wd, const float* __restrict__ db,
    const float* __restrict__ bng, const float* __restrict__ bnb,
    const float* __restrict__ bnm, const float* __restrict__ bnv,
    float* __restrict__ out)
{
    extern __shared__ float sm[];
    float* s_x     = sm;                    // CC*5*XROW = 8960 f
    float* s_xm    = s_x   + CC*5*XROW;     // CC*XMS    = 8448 f
    u64*   s_wd2   = reinterpret_cast<u64*>(s_xm + CC*XMS);  // 4096 ull
    float* s_Aad   = reinterpret_cast<float*>(s_wd2 + CC*OCn); // 28*32 f
    float* s_scale = s_Aad + 28*32;
    float* s_off   = s_scale + 64;

    const int tid  = threadIdx.x;
    const int wid  = tid >> 5;
    const int lane = tid & 31;
    const int tb = blockIdx.x;
    const int n  = blockIdx.y;
    const int t0 = tb * TTB;

    const float* xb = x + (size_t)n*(CC*TD*VV) + (size_t)t0*VV;

    // x tile: [c][lt][v] padded rows of XROW
    for (int idx = tid; idx < CC*COLB; idx += 256) {
        int c = idx / COLB, col = idx % COLB;
        int lt = col / 25, v = col - lt*25;
        s_x[(c*5 + lt)*XROW + v] = xb[(size_t)c*(TD*VV) + col];
    }
    for (int idx = tid; idx < CC*5*3; idx += 256) {
        int row = idx / 3, p = idx % 3;
        s_x[row*XROW + 25 + p] = 0.f;
    }
    for (int idx = tid; idx < CC*XMS; idx += 256) s_xm[idx] = 0.f;
    if (tid < OCn) {
        float sc = bng[tid] * rsqrtf(bnv[tid] + EPSF);
        float ds = db[tid] + db[OCn + tid] + db[2*OCn + tid];
        s_scale[tid] = sc;
        s_off[tid]   = (ds - bnm[tid]) * sc + bnb[tid];
    }

    u64 yacc[8][2];
    #pragma unroll
    for (int r = 0; r < 8; r++) { yacc[r][0] = 0ull; yacc[r][1] = 0ull; }

    for (int s = 0; s < SS; s++) {
        __syncthreads();
        // A_adp padded [28][32], zeros outside 25x25
        for (int idx = tid; idx < 28*32; idx += 256) {
            int v = idx >> 5, w = idx & 31;
            s_Aad[idx] = (v < VV && w < VV)
                       ? g_Aadp[((size_t)n*SS + s)*(VV*VV) + v*VV + w] : 0.f;
        }
        // duplicated weight pairs: s_wd2[c*64+o] = (w, w)
        for (int idx = tid; idx < CC*OCn; idx += 256) {
            int c = idx >> 6, o = idx & 63;
            float wv = wd[s*(OCn*CC) + o*CC + c];
            s_wd2[c*OCn + o] = pack2(wv, wv);
        }
        __syncthreads();

        // GEMM1: xm[c][lt*25+w] = sum_v x[c][lt][v]*Aad[v][w]
        // thread: c in {lane, lane+32}, w pairs (wid*4,+1),(+2,+3)
        for (int lt = 0; lt < TTB; lt++) {
            u64 a0[2] = {0ull, 0ull};
            u64 a1[2] = {0ull, 0ull};
            const float* xp0 = &s_x[(lane*5 + lt)*XROW];
            const float* xp1 = &s_x[((lane+32)*5 + lt)*XROW];
            #pragma unroll
            for (int v4 = 0; v4 < 7; v4++) {
                float4 x0 = *reinterpret_cast<const float4*>(xp0 + v4*4);
                float4 x1 = *reinterpret_cast<const float4*>(xp1 + v4*4);
                #pragma unroll
                for (int vv = 0; vv < 4; vv++) {
                    ulonglong2 aa = *reinterpret_cast<const ulonglong2*>(
                        &s_Aad[(v4*4+vv)*32 + wid*4]);
                    float xs0 = (&x0.x)[vv], xs1 = (&x1.x)[vv];
                    u64 xd0 = pack2(xs0, xs0);
                    u64 xd1 = pack2(xs1, xs1);
                    fma2(a0[0], xd0, aa.x);
                    fma2(a0[1], xd0, aa.y);
                    fma2(a1[0], xd1, aa.x);
                    fma2(a1[1], xd1, aa.y);
                }
            }
            float2 p00 = unpack2(a0[0]), p01 = unpack2(a0[1]);
            float2 p10 = unpack2(a1[0]), p11 = unpack2(a1[1]);
            int w = wid*4;
            if (w < VV) {
                s_xm[lane*XMS      + lt*25 + w] = p00.x;
                s_xm[(lane+32)*XMS + lt*25 + w] = p10.x;
            }
            if (w+1 < VV) {
                s_xm[lane*XMS      + lt*25 + w+1] = p00.y;
                s_xm[(lane+32)*XMS + lt*25 + w+1] = p10.y;
            }
            if (w+2 < VV) {
                s_xm[lane*XMS      + lt*25 + w+2] = p01.x;
                s_xm[(lane+32)*XMS + lt*25 + w+2] = p11.x;
            }
            if (w+3 < VV) {
                s_xm[lane*XMS      + lt*25 + w+3] = p01.y;
                s_xm[(lane+32)*XMS + lt*25 + w+3] = p11.y;
            }
        }
        __syncthreads();

        // GEMM2: y[o][col] += wdT[c][o]*xm[c][col]; col pairs (lane*4..+3)
        #pragma unroll 4
        for (int c = 0; c < CC; c++) {
            ulonglong2 xm2 = *reinterpret_cast<const ulonglong2*>(
                &s_xm[c*XMS + lane*4]);
            const ulonglong2* wrow = reinterpret_cast<const ulonglong2*>(
                &s_wd2[c*OCn + wid*8]);
            #pragma unroll
            for (int r2 = 0; r2 < 4; r2++) {
                ulonglong2 wp = wrow[r2];
                fma2(yacc[2*r2][0],   wp.x, xm2.x);
                fma2(yacc[2*r2][1],   wp.x, xm2.y);
                fma2(yacc[2*r2+1][0], wp.y, xm2.x);
                fma2(yacc[2*r2+1][1], wp.y, xm2.y);
            }
        }
    }

    // Epilogue: BN + residual + ReLU
    float* ob = out + (size_t)n*(CC*TD*VV) + (size_t)t0*VV;
    #pragma unroll
    for (int r = 0; r < 8; r++) {
        int o = wid*8 + r;
        float sc = s_scale[o], of = s_off[o];
        float2 y0 = unpack2(yacc[r][0]);
        float2 y1 = unpack2(yacc[r][1]);
        float yv[4] = {y0.x, y0.y, y1.x, y1.y};
        #pragma unroll
        for (int j = 0; j < 4; j++) {
            int col = lane*4 + j;
            if (col < COLB) {
                int lt = col / 25, v = col - lt*25;
                float val = yv[j]*sc + of + s_x[(o*5 + lt)*XROW + v];
                ob[(size_t)o*(TD*VV) + col] = fmaxf(val, 0.f);
            }
        }
    }
}

// ---------------------------------------------------------------------------
extern "C" void kernel_launch(void* const* d_in, const int* in_sizes, int n_in,
                              void* d_out, int out_size)
{
    const float* x     = (const float*)d_in[0];
    const float* A     = (const float*)d_in[1];
    const float* alpha = (const float*)d_in[2];
    const float* caw   = (const float*)d_in[3];
    const float* cab   = (const float*)d_in[4];
    const float* cbw   = (const float*)d_in[5];
    const float* cbb   = (const float*)d_in[6];
    const float* bag   = (const float*)d_in[7];
    const float* babt  = (const float*)d_in[8];
    const float* bam   = (const float*)d_in[9];
    const float* bav   = (const float*)d_in[10];
    const float* bbg   = (const float*)d_in[11];
    const float* bbbt  = (const float*)d_in[12];
    const float* bbm   = (const float*)d_in[13];
    const float* bbv   = (const float*)d_in[14];
    const float* cdw   = (const float*)d_in[15];
    const float* cdb   = (const float*)d_in[16];
    const float* bng   = (const float*)d_in[17];
    const float* bnb   = (const float*)d_in[18];
    const float* bnm   = (const float*)d_in[19];
    const float* bnv   = (const float*)d_in[20];
    float* out = (float*)d_out;

    const int smemB = (CC*5*XROW + CC*XMS) * sizeof(float)
                    + CC*OCn * sizeof(u64)
                    + (28*32 + 64 + 64) * sizeof(float);
    cudaFuncSetAttribute(kB, cudaFuncAttributeMaxDynamicSharedMemorySize, smemB);

    kA<<<dim3(NCH, SS, NN), 256>>>(x, caw, cab, cbw, cbb,
                                   bag, babt, bam, bav,
                                   bbg, bbbt, bbm, bbv);
    kA2<<<(NN*SS*VV*VV + 255)/256, 256>>>(A, alpha);
    kB<<<dim3(NTB, NN), 256, smemB>>>(x, cdw, cdb, bng, bnb, bnm, bnv, out);
}

// round 4
// speedup vs baseline: 1.1016x; 1.1016x over previous
#include <cuda_runtime.h>

#define EPSF 1e-5f

// Problem dims
#define NN  64
#define CC  64
#define TD  300
#define VV  25
#define SS  3
#define ICn 16
#define OCn 64

// Kernel A tiling
#define TTA    10             // t's per subtile
#define SUBS   10             // subtiles per block
#define TCHUNK (TTA*SUBS)     // 100 t's per block
#define NCH    3              // TD / TCHUNK
#define COLA   (TTA*VV)       // 250 flattened cols per subtile
#define ABS_R  28             // padded row stride for s_a/s_b
#define KROWS  (ICn*TTA)      // 160

// Kernel B tiling
#define TTB  5
#define COLB (TTB*VV)         // 125
#define XMS  132              // padded xm row stride (16B aligned)
#define NTB  (TD/TTB)         // 60
#define XROW 28               // padded per-(c,lt) x row

typedef unsigned long long u64;

__device__ float g_Mpart[NCH*NN*SS*VV*VV];
__device__ float g_Aadp [NN*SS*VV*VV];

__device__ __forceinline__ float tanh_fast(float x) {
    float y;
    asm("tanh.approx.f32 %0, %1;" : "=f"(y) : "f"(x));
    return y;
}
__device__ __forceinline__ u64 pack2(float lo, float hi) {
    u64 r; asm("mov.b64 %0, {%1, %2};" : "=l"(r) : "f"(lo), "f"(hi)); return r;
}
__device__ __forceinline__ float2 unpack2(u64 p) {
    float2 r; asm("mov.b64 {%0, %1}, %2;" : "=f"(r.x), "=f"(r.y) : "l"(p)); return r;
}
__device__ __forceinline__ void fma2(u64& d, u64 a, u64 b) {
    asm("fma.rn.f32x2 %0, %1, %2, %0;" : "+l"(d) : "l"(a), "l"(b));
}

// ---------------------------------------------------------------------------
// Kernel A: per (chunk, s, n): a = tanh(bn(Wa x)), b = tanh(bn(Wb x)),
// partial M[v,w] += a^T b over 100 t's.
// Conv: thread = (i-halfgroup, col-pair). i paired (natural smem pairs),
// x LDG.64 per col-pair, dup'd in registers.
// ---------------------------------------------------------------------------
__global__ __launch_bounds__(256) void kA(
    const float* __restrict__ x,
    const float* __restrict__ wa, const float* __restrict__ ba,
    const float* __restrict__ wb, const float* __restrict__ bb,
    const float* __restrict__ gag, const float* __restrict__ gab,
    const float* __restrict__ gam, const float* __restrict__ gav,
    const float* __restrict__ gbg, const float* __restrict__ gbb,
    const float* __restrict__ gbm, const float* __restrict__ gbv)
{
    __shared__ __align__(16) float s_w[CC*32];   // [c][0..15]=wa', [16..31]=wb'
    __shared__ float s_sha[ICn], s_shb[ICn];
    __shared__ __align__(16) float s_a[KROWS*ABS_R + 8];
    __shared__ __align__(16) float s_b[KROWS*ABS_R + 8];

    const int tid  = threadIdx.x;
    const int wid  = tid >> 5;
    const int lane = tid & 31;
    const int chunk = blockIdx.x;
    const int s     = blockIdx.y;
    const int n     = blockIdx.z;

    // Fold BN into weights
    for (int idx = tid; idx < ICn*CC; idx += 256) {
        int i = idx / CC, c = idx % CC;
        float sca = gag[s*ICn+i] * rsqrtf(gav[s*ICn+i] + EPSF);
        float scb = gbg[s*ICn+i] * rsqrtf(gbv[s*ICn+i] + EPSF);
        s_w[c*32 + i]      = wa[s*ICn*CC + idx] * sca;
        s_w[c*32 + 16 + i] = wb[s*ICn*CC + idx] * scb;
    }
    if (tid < ICn) {
        float sca = gag[s*ICn+tid] * rsqrtf(gav[s*ICn+tid] + EPSF);
        float scb = gbg[s*ICn+tid] * rsqrtf(gbv[s*ICn+tid] + EPSF);
        s_sha[tid] = (ba[s*ICn+tid] - gam[s*ICn+tid]) * sca + gab[s*ICn+tid];
        s_shb[tid] = (bb[s*ICn+tid] - gbm[s*ICn+tid]) * scb + gbb[s*ICn+tid];
    }

    // Conv thread mapping: 250 active = 2 i-halfgroups x 125 col-pairs
    const int igrp = tid / 125;          // 0..1
    const int cp   = tid - igrp*125;     // 0..124
    const int col0 = 2*cp;
    const int lt0  = col0 / 25, v0 = col0 - lt0*25;
    const int lt1  = (col0+1) / 25, v1 = (col0+1) - lt1*25;
    const int i0   = igrp*8;
    const bool act = (tid < 250);

    // Persistent M accumulators: lane = v, w pairs (wid*4,+1),(+2,+3)
    u64 maccP[2] = {0ull, 0ull};

    const float* xbase = x + (size_t)n*(CC*TD*VV) + (size_t)(chunk*TCHUNK)*VV;

    for (int sub = 0; sub < SUBS; sub++) {
        __syncthreads();   // prior M-acc reads finished before overwrite
        if (act) {
            // acc[A/B][pair p][col h]: pair over (i0+2p, i0+2p+1)
            u64 accA0[4], accA1[4], accB0[4], accB1[4];
            #pragma unroll
            for (int p = 0; p < 4; p++) {
                u64 ia = pack2(s_sha[i0+2*p], s_sha[i0+2*p+1]);
                u64 ib = pack2(s_shb[i0+2*p], s_shb[i0+2*p+1]);
                accA0[p] = ia; accA1[p] = ia;
                accB0[p] = ib; accB1[p] = ib;
            }
            const float* xp = xbase + sub*COLA + col0;
            #pragma unroll 4
            for (int c = 0; c < CC; c++) {
                float2 xv = *reinterpret_cast<const float2*>(xp + (size_t)c*(TD*VV));
                u64 xd0 = pack2(xv.x, xv.x);
                u64 xd1 = pack2(xv.y, xv.y);
                ulonglong2 wa2 = *reinterpret_cast<const ulonglong2*>(&s_w[c*32 + i0]);
                ulonglong2 wa3 = *reinterpret_cast<const ulonglong2*>(&s_w[c*32 + i0 + 4]);
                ulonglong2 wb2 = *reinterpret_cast<const ulonglong2*>(&s_w[c*32 + 16 + i0]);
                ulonglong2 wb3 = *reinterpret_cast<const ulonglong2*>(&s_w[c*32 + 16 + i0 + 4]);
                fma2(accA0[0], wa2.x, xd0); fma2(accA1[0], wa2.x, xd1);
                fma2(accA0[1], wa2.y, xd0); fma2(accA1[1], wa2.y, xd1);
                fma2(accA0[2], wa3.x, xd0); fma2(accA1[2], wa3.x, xd1);
                fma2(accA0[3], wa3.y, xd0); fma2(accA1[3], wa3.y, xd1);
                fma2(accB0[0], wb2.x, xd0); fma2(accB1[0], wb2.x, xd1);
                fma2(accB0[1], wb2.y, xd0); fma2(accB1[1], wb2.y, xd1);
                fma2(accB0[2], wb3.x, xd0); fma2(accB1[2], wb3.x, xd1);
                fma2(accB0[3], wb3.y, xd0); fma2(accB1[3], wb3.y, xd1);
            }
            #pragma unroll
            for (int p = 0; p < 4; p++) {
                float2 a0 = unpack2(accA0[p]);
                float2 a1 = unpack2(accA1[p]);
                float2 b0 = unpack2(accB0[p]);
                float2 b1 = unpack2(accB1[p]);
                int ie = i0 + 2*p, io = ie + 1;
                s_a[(ie*TTA + lt0)*ABS_R + v0] = tanh_fast(a0.x);
                s_a[(io*TTA + lt0)*ABS_R + v0] = tanh_fast(a0.y);
                s_a[(ie*TTA + lt1)*ABS_R + v1] = tanh_fast(a1.x);
                s_a[(io*TTA + lt1)*ABS_R + v1] = tanh_fast(a1.y);
                s_b[(ie*TTA + lt0)*ABS_R + v0] = tanh_fast(b0.x);
                s_b[(io*TTA + lt0)*ABS_R + v0] = tanh_fast(b0.y);
                s_b[(ie*TTA + lt1)*ABS_R + v1] = tanh_fast(b1.x);
                s_b[(io*TTA + lt1)*ABS_R + v1] = tanh_fast(b1.y);
            }
        }
        __syncthreads();

        // M accumulate over K = 160 rows
        #pragma unroll 4
        for (int kk = 0; kk < KROWS; kk++) {
            float av = s_a[kk*ABS_R + lane];
            u64 avp = pack2(av, av);
            ulonglong2 bv = *reinterpret_cast<const ulonglong2*>(
                &s_b[kk*ABS_R + wid*4]);
            fma2(maccP[0], avp, bv.x);
            fma2(maccP[1], avp, bv.y);
        }
    }

    if (lane < VV) {
        float* mp = &g_Mpart[((size_t)chunk*NN*SS + (size_t)n*SS + s)*(VV*VV)];
        float2 m0 = unpack2(maccP[0]);
        float2 m1 = unpack2(maccP[1]);
        int w = wid*4;
        if (w   < VV) mp[lane*VV + w]   = m0.x;
        if (w+1 < VV) mp[lane*VV + w+1] = m0.y;
        if (w+2 < VV) mp[lane*VV + w+2] = m1.x;
        if (w+3 < VV) mp[lane*VV + w+3] = m1.y;
    }
}

// ---------------------------------------------------------------------------
// Kernel A2: reduce partials, A_adp = A + tanh(M/(IC*T)) * alpha
// ---------------------------------------------------------------------------
__global__ void kA2(const float* __restrict__ A, const float* __restrict__ alpha)
{
    int idx = blockIdx.x * 256 + threadIdx.x;
    if (idx >= NN*SS*VV*VV) return;
    float m = 0.f;
    #pragma unroll
    for (int ch = 0; ch < NCH; ch++)
        m += g_Mpart[ch*(NN*SS*VV*VV) + idx];
    g_Aadp[idx] = A[idx % (SS*VV*VV)]
                + tanhf(m * (1.f/(float)(ICn*TD))) * alpha[0];
}

// ---------------------------------------------------------------------------
// Kernel B: per (t-tile, n): for each s: xm = x_tile @ A_adp (K=25),
// y += WdT @ xm (K=64). GEMM2 pairs over o (natural), xm dup in regs.
// ---------------------------------------------------------------------------
__global__ __launch_bounds__(256) void kB(
    const float* __restrict__ x,
    const float* __restrict__ wd, const float* __restrict__ db,
    const float* __restrict__ bng, const float* __restrict__ bnb,
    const float* __restrict__ bnm, const float* __restrict__ bnv,
    float* __restrict__ out)
{
    extern __shared__ float sm[];
    float* s_x     = sm;                    // CC*5*XROW = 8960
    float* s_xm    = s_x   + CC*5*XROW;     // CC*XMS    = 8448
    float* s_wdT   = s_xm  + CC*XMS;        // CC*68     = 4352 (o contiguous)
    float* s_Aad   = s_wdT + CC*68;         // 28*32     = 896
    float* s_scale = s_Aad + 28*32;         // 64
    float* s_off   = s_scale + 64;          // 64

    const int tid  = threadIdx.x;
    const int wid  = tid >> 5;
    const int lane = tid & 31;
    const int tb = blockIdx.x;
    const int n  = blockIdx.y;
    const int t0 = tb * TTB;

    const float* xb = x + (size_t)n*(CC*TD*VV) + (size_t)t0*VV;

    // x tile: [c][lt][v] padded rows of XROW
    for (int idx = tid; idx < CC*COLB; idx += 256) {
        int c = idx / COLB, col = idx % COLB;
        int lt = col / 25, v = col - lt*25;
        s_x[(c*5 + lt)*XROW + v] = xb[(size_t)c*(TD*VV) + col];
    }
    for (int idx = tid; idx < CC*5*3; idx += 256) {
        int row = idx / 3, p = idx % 3;
        s_x[row*XROW + 25 + p] = 0.f;
    }
    for (int idx = tid; idx < CC*XMS; idx += 256) s_xm[idx] = 0.f;
    if (tid < OCn) {
        float sc = bng[tid] * rsqrtf(bnv[tid] + EPSF);
        float ds = db[tid] + db[OCn + tid] + db[2*OCn + tid];
        s_scale[tid] = sc;
        s_off[tid]   = (ds - bnm[tid]) * sc + bnb[tid];
    }

    // yacc[o-pair p][col j]: o = wid*8 + 2p + half, col = lane*4 + j
    u64 yacc[4][4];
    #pragma unroll
    for (int p = 0; p < 4; p++)
        #pragma unroll
        for (int j = 0; j < 4; j++) yacc[p][j] = 0ull;

    for (int s = 0; s < SS; s++) {
        __syncthreads();
        // A_adp padded [28][32], zeros outside 25x25
        for (int idx = tid; idx < 28*32; idx += 256) {
            int v = idx >> 5, w = idx & 31;
            s_Aad[idx] = (v < VV && w < VV)
                       ? g_Aadp[((size_t)n*SS + s)*(VV*VV) + v*VV + w] : 0.f;
        }
        // weights transposed [c][o], o contiguous (natural o-pairs)
        for (int idx = tid; idx < CC*OCn; idx += 256) {
            int o = idx >> 6, c = idx & 63;
            s_wdT[c*68 + o] = wd[s*(OCn*CC) + idx];
        }
        __syncthreads();

        // GEMM1: xm[c][lt*25+w] = sum_v x[c][lt][v]*Aad[v][w]
        // thread: c in {lane, lane+32}, w pairs (wid*4,+1),(+2,+3)
        for (int lt = 0; lt < TTB; lt++) {
            u64 a0[2] = {0ull, 0ull};
            u64 a1[2] = {0ull, 0ull};
            const float* xp0 = &s_x[(lane*5 + lt)*XROW];
            const float* xp1 = &s_x[((lane+32)*5 + lt)*XROW];
            #pragma unroll
            for (int v4 = 0; v4 < 7; v4++) {
                float4 x0 = *reinterpret_cast<const float4*>(xp0 + v4*4);
                float4 x1 = *reinterpret_cast<const float4*>(xp1 + v4*4);
                #pragma unroll
                for (int vv = 0; vv < 4; vv++) {
                    ulonglong2 aa = *reinterpret_cast<const ulonglong2*>(
                        &s_Aad[(v4*4+vv)*32 + wid*4]);
                    float xs0 = (&x0.x)[vv], xs1 = (&x1.x)[vv];
                    u64 xd0 = pack2(xs0, xs0);
                    u64 xd1 = pack2(xs1, xs1);
                    fma2(a0[0], xd0, aa.x);
                    fma2(a0[1], xd0, aa.y);
                    fma2(a1[0], xd1, aa.x);
                    fma2(a1[1], xd1, aa.y);
                }
            }
            float2 p00 = unpack2(a0[0]), p01 = unpack2(a0[1]);
            float2 p10 = unpack2(a1[0]), p11 = unpack2(a1[1]);
            int w = wid*4;
            if (w < VV) {
                s_xm[lane*XMS      + lt*25 + w] = p00.x;
                s_xm[(lane+32)*XMS + lt*25 + w] = p10.x;
            }
            if (w+1 < VV) {
                s_xm[lane*XMS      + lt*25 + w+1] = p00.y;
                s_xm[(lane+32)*XMS + lt*25 + w+1] = p10.y;
            }
            if (w+2 < VV) {
                s_xm[lane*XMS      + lt*25 + w+2] = p01.x;
                s_xm[(lane+32)*XMS + lt*25 + w+2] = p11.x;
            }
            if (w+3 < VV) {
                s_xm[lane*XMS      + lt*25 + w+3] = p01.y;
                s_xm[(lane+32)*XMS + lt*25 + w+3] = p11.y;
            }
        }
        __syncthreads();

        // GEMM2: y[o][col] += wdT[c][o]*xm[c][col]
        // o-pairs natural from s_wdT; xm scalars dup'd in regs
        #pragma unroll 4
        for (int c = 0; c < CC; c++) {
            float4 xmv = *reinterpret_cast<const float4*>(&s_xm[c*XMS + lane*4]);
            u64 xd0 = pack2(xmv.x, xmv.x);
            u64 xd1 = pack2(xmv.y, xmv.y);
            u64 xd2 = pack2(xmv.z, xmv.z);
            u64 xd3 = pack2(xmv.w, xmv.w);
            ulonglong2 w01 = *reinterpret_cast<const ulonglong2*>(
                &s_wdT[c*68 + wid*8]);
            ulonglong2 w23 = *reinterpret_cast<const ulonglong2*>(
                &s_wdT[c*68 + wid*8 + 4]);
            fma2(yacc[0][0], w01.x, xd0); fma2(yacc[0][1], w01.x, xd1);
            fma2(yacc[0][2], w01.x, xd2); fma2(yacc[0][3], w01.x, xd3);
            fma2(yacc[1][0], w01.y, xd0); fma2(yacc[1][1], w01.y, xd1);
            fma2(yacc[1][2], w01.y, xd2); fma2(yacc[1][3], w01.y, xd3);
            fma2(yacc[2][0], w23.x, xd0); fma2(yacc[2][1], w23.x, xd1);
            fma2(yacc[2][2], w23.x, xd2); fma2(yacc[2][3], w23.x, xd3);
            fma2(yacc[3][0], w23.y, xd0); fma2(yacc[3][1], w23.y, xd1);
            fma2(yacc[3][2], w23.y, xd2); fma2(yacc[3][3], w23.y, xd3);
        }
    }

    // Epilogue: BN + residual + ReLU
    float* ob = out + (size_t)n*(CC*TD*VV) + (size_t)t0*VV;
    #pragma unroll
    for (int p = 0; p < 4; p++) {
        int oe = wid*8 + 2*p, oo = oe + 1;
        float sce = s_scale[oe], ofe = s_off[oe];
        float sco = s_scale[oo], ofo = s_off[oo];
        #pragma unroll
        for (int j = 0; j < 4; j++) {
            int col = lane*4 + j;
            if (col < COLB) {
                int lt = col / 25, v = col - lt*25;
                float2 y2 = unpack2(yacc[p][j]);
                float ve = y2.x*sce + ofe + s_x[(oe*5 + lt)*XROW + v];
                float vo = y2.y*sco + ofo + s_x[(oo*5 + lt)*XROW + v];
                ob[(size_t)oe*(TD*VV) + col] = fmaxf(ve, 0.f);
                ob[(size_t)oo*(TD*VV) + col] = fmaxf(vo, 0.f);
            }
        }
    }
}

// ---------------------------------------------------------------------------
extern "C" void kernel_launch(void* const* d_in, const int* in_sizes, int n_in,
                              void* d_out, int out_size)
{
    const float* x     = (const float*)d_in[0];
    const float* A     = (const float*)d_in[1];
    const float* alpha = (const float*)d_in[2];
    const float* caw   = (const float*)d_in[3];
    const float* cab   = (const float*)d_in[4];
    const float* cbw   = (const float*)d_in[5];
    const float* cbb   = (const float*)d_in[6];
    const float* bag   = (const float*)d_in[7];
    const float* babt  = (const float*)d_in[8];
    const float* bam   = (const float*)d_in[9];
    const float* bav   = (const float*)d_in[10];
    const float* bbg   = (const float*)d_in[11];
    const float* bbbt  = (const float*)d_in[12];
    const float* bbm   = (const float*)d_in[13];
    const float* bbv   = (const float*)d_in[14];
    const float* cdw   = (const float*)d_in[15];
    const float* cdb   = (const float*)d_in[16];
    const float* bng   = (const float*)d_in[17];
    const float* bnb   = (const float*)d_in[18];
    const float* bnm   = (const float*)d_in[19];
    const float* bnv   = (const float*)d_in[20];
    float* out = (float*)d_out;

    const int smemB = (CC*5*XROW + CC*XMS + CC*68 + 28*32 + 64 + 64) * sizeof(float);
    cudaFuncSetAttribute(kB, cudaFuncAttributeMaxDynamicSharedMemorySize, smemB);

    kA<<<dim3(NCH, SS, NN), 256>>>(x, caw, cab, cbw, cbb,
                                   bag, babt, bam, bav,
                                   bbg, bbbt, bbm, bbv);
    kA2<<<(NN*SS*VV*VV + 255)/256, 256>>>(A, alpha);
    kB<<<dim3(NTB, NN), 256, smemB>>>(x, cdw, cdb, bng, bnb, bnm, bnv, out);
}

// round 5
// speedup vs baseline: 1.2769x; 1.1591x over previous
#include <cuda_runtime.h>
#include <cuda_bf16.h>

#define EPSF 1e-5f

// Problem dims
#define NN  64
#define CC  64
#define TD  300
#define VV  25
#define SS  3
#define ICn 16
#define OCn 64

// kConv tiling
#define TCB   20              // t's per block
#define NTCB  (TD/TCB)        // 15
#define COLSB (TCB*VV)        // 500 columns per block

// kM tiling
#define NCH  5
#define KTOT (ICn*TD)         // 4800 rows per (n,s)
#define KCH  (KTOT/NCH)       // 960 rows per chunk
#define KST  64               // rows per stage
#define NSTG (KCH/KST)        // 15

// kB tiling (round-4, unchanged)
#define TTB  5
#define COLB (TTB*VV)         // 125
#define XMS  132
#define NTB  (TD/TTB)         // 60
#define XROW 28

typedef unsigned long long u64;

// a,b interleaved as bf16 pairs: g_ab[(n*S+s)*4800 + t*16 + i][v(pad 32)] = (a, b)
__device__ __nv_bfloat162 g_ab[(size_t)NN*SS*KTOT*32];
__device__ float g_Mpart[NCH*NN*SS*VV*VV];
__device__ float g_Aadp [NN*SS*VV*VV];

__device__ __forceinline__ float tanh_fast(float x) {
    float y;
    asm("tanh.approx.f32 %0, %1;" : "=f"(y) : "f"(x));
    return y;
}
__device__ __forceinline__ u64 pack2(float lo, float hi) {
    u64 r; asm("mov.b64 %0, {%1, %2};" : "=l"(r) : "f"(lo), "f"(hi)); return r;
}
__device__ __forceinline__ float2 unpack2(u64 p) {
    float2 r; asm("mov.b64 {%0, %1}, %2;" : "=f"(r.x), "=f"(r.y) : "l"(p)); return r;
}
__device__ __forceinline__ void fma2(u64& d, u64 a, u64 b) {
    asm("fma.rn.f32x2 %0, %1, %2, %0;" : "+l"(d) : "l"(a), "l"(b));
}

// ---------------------------------------------------------------------------
// kConv: a = tanh(bn(Wa x)), b = tanh(bn(Wb x)) -> g_ab (bf16 pairs).
// Streaming, no barriers in main loop. Thread = 2 cols x all 16 i's.
// ---------------------------------------------------------------------------
__global__ __launch_bounds__(256) void kConv(
    const float* __restrict__ x,
    const float* __restrict__ wa, const float* __restrict__ ba,
    const float* __restrict__ wb, const float* __restrict__ bb,
    const float* __restrict__ gag, const float* __restrict__ gab,
    const float* __restrict__ gam, const float* __restrict__ gav,
    const float* __restrict__ gbg, const float* __restrict__ gbb,
    const float* __restrict__ gbm, const float* __restrict__ gbv)
{
    __shared__ __align__(16) float s_w[CC*32];   // [c][0..15]=wa', [16..31]=wb'
    __shared__ float s_sha[ICn], s_shb[ICn];

    const int tid = threadIdx.x;
    const int tc  = blockIdx.x;
    const int s   = blockIdx.y;
    const int n   = blockIdx.z;

    for (int idx = tid; idx < ICn*CC; idx += 256) {
        int i = idx / CC, c = idx % CC;
        float sca = gag[s*ICn+i] * rsqrtf(gav[s*ICn+i] + EPSF);
        float scb = gbg[s*ICn+i] * rsqrtf(gbv[s*ICn+i] + EPSF);
        s_w[c*32 + i]      = wa[s*ICn*CC + idx] * sca;
        s_w[c*32 + 16 + i] = wb[s*ICn*CC + idx] * scb;
    }
    if (tid < ICn) {
        float sca = gag[s*ICn+tid] * rsqrtf(gav[s*ICn+tid] + EPSF);
        float scb = gbg[s*ICn+tid] * rsqrtf(gbv[s*ICn+tid] + EPSF);
        s_sha[tid] = (ba[s*ICn+tid] - gam[s*ICn+tid]) * sca + gab[s*ICn+tid];
        s_shb[tid] = (bb[s*ICn+tid] - gbm[s*ICn+tid]) * scb + gbb[s*ICn+tid];
    }
    __syncthreads();
    if (tid >= COLSB/2) return;          // 250 active; no barriers after this

    const int col0 = tc*COLSB + 2*tid;
    const int col1 = col0 + 1;
    const int t0 = col0 / 25, v0 = col0 - 25*t0;
    const int t1 = col1 / 25, v1 = col1 - 25*t1;

    // 8 i-pairs per col for a and b: 32 packed accumulators
    u64 accA0[8], accA1[8], accB0[8], accB1[8];
    #pragma unroll
    for (int p = 0; p < 8; p++) {
        u64 ia = pack2(s_sha[2*p], s_sha[2*p+1]);
        u64 ib = pack2(s_shb[2*p], s_shb[2*p+1]);
        accA0[p] = ia; accA1[p] = ia;
        accB0[p] = ib; accB1[p] = ib;
    }

    const float* xp = x + (size_t)n*(CC*TD*VV) + col0;
    #pragma unroll 4
    for (int c = 0; c < CC; c++) {
        float2 xv = *reinterpret_cast<const float2*>(xp + (size_t)c*(TD*VV));
        u64 xd0 = pack2(xv.x, xv.x);
        u64 xd1 = pack2(xv.y, xv.y);
        const ulonglong2* wrow = reinterpret_cast<const ulonglong2*>(&s_w[c*32]);
        #pragma unroll
        for (int g = 0; g < 4; g++) {
            ulonglong2 w2 = wrow[g];           // a i-pairs 2g, 2g+1
            fma2(accA0[2*g],   w2.x, xd0); fma2(accA1[2*g],   w2.x, xd1);
            fma2(accA0[2*g+1], w2.y, xd0); fma2(accA1[2*g+1], w2.y, xd1);
        }
        #pragma unroll
        for (int g = 0; g < 4; g++) {
            ulonglong2 w2 = wrow[4+g];         // b i-pairs 2g, 2g+1
            fma2(accB0[2*g],   w2.x, xd0); fma2(accB1[2*g],   w2.x, xd1);
            fma2(accB0[2*g+1], w2.y, xd0); fma2(accB1[2*g+1], w2.y, xd1);
        }
    }

    __nv_bfloat162* gb = g_ab + (size_t)(n*SS + s)*KTOT*32;
    #pragma unroll
    for (int p = 0; p < 8; p++) {
        float2 a0 = unpack2(accA0[p]);
        float2 b0 = unpack2(accB0[p]);
        float2 a1 = unpack2(accA1[p]);
        float2 b1 = unpack2(accB1[p]);
        __nv_bfloat162 h;
        h.x = __float2bfloat16(tanh_fast(a0.x));
        h.y = __float2bfloat16(tanh_fast(b0.x));
        gb[(size_t)(t0*ICn + 2*p)*32 + v0] = h;
        h.x = __float2bfloat16(tanh_fast(a0.y));
        h.y = __float2bfloat16(tanh_fast(b0.y));
        gb[(size_t)(t0*ICn + 2*p+1)*32 + v0] = h;
        h.x = __float2bfloat16(tanh_fast(a1.x));
        h.y = __float2bfloat16(tanh_fast(b1.x));
        gb[(size_t)(t1*ICn + 2*p)*32 + v1] = h;
        h.x = __float2bfloat16(tanh_fast(a1.y));
        h.y = __float2bfloat16(tanh_fast(b1.y));
        gb[(size_t)(t1*ICn + 2*p+1)*32 + v1] = h;
    }
}

// ---------------------------------------------------------------------------
// kM: partial M[v,w] = sum_k a[k,v]*b[k,w] over this chunk's 960 rows.
// Stage 64 bf16-pair rows -> fp32 smem, then packed FMA2 rank-updates.
// ---------------------------------------------------------------------------
__global__ __launch_bounds__(256) void kM()
{
    __shared__ __align__(16) float s_a32[KST*32];
    __shared__ __align__(16) float s_b32[KST*32];

    const int tid  = threadIdx.x;
    const int wid  = tid >> 5;
    const int lane = tid & 31;
    const int chunk = blockIdx.x;
    const int s     = blockIdx.y;
    const int n     = blockIdx.z;

    const uint4* gsrc = reinterpret_cast<const uint4*>(
        g_ab + ((size_t)(n*SS + s)*KTOT + (size_t)chunk*KCH)*32);

    u64 macc[2] = {0ull, 0ull};

    for (int st = 0; st < NSTG; st++) {
        __syncthreads();
        #pragma unroll
        for (int rep = 0; rep < 2; rep++) {
            int u = tid + rep*256;                 // 0..511 uint4 per stage
            uint4 val = gsrc[st*512 + u];
            int row = u >> 3, q = u & 7;
            float* pa = &s_a32[row*32 + q*4];
            float* pb = &s_b32[row*32 + q*4];
            float2 f0 = __bfloat1622float2(*reinterpret_cast<__nv_bfloat162*>(&val.x));
            float2 f1 = __bfloat1622float2(*reinterpret_cast<__nv_bfloat162*>(&val.y));
            float2 f2 = __bfloat1622float2(*reinterpret_cast<__nv_bfloat162*>(&val.z));
            float2 f3 = __bfloat1622float2(*reinterpret_cast<__nv_bfloat162*>(&val.w));
            pa[0] = f0.x; pb[0] = f0.y;
            pa[1] = f1.x; pb[1] = f1.y;
            pa[2] = f2.x; pb[2] = f2.y;
            pa[3] = f3.x; pb[3] = f3.y;
        }
        __syncthreads();
        #pragma unroll 8
        for (int kk = 0; kk < KST; kk++) {
            float av = s_a32[kk*32 + lane];
            u64 ap = pack2(av, av);
            ulonglong2 bv = *reinterpret_cast<const ulonglong2*>(
                &s_b32[kk*32 + wid*4]);
            fma2(macc[0], ap, bv.x);
            fma2(macc[1], ap, bv.y);
        }
    }

    if (lane < VV) {
        float* mp = &g_Mpart[((size_t)chunk*NN*SS + (size_t)n*SS + s)*(VV*VV)];
        float2 m0 = unpack2(macc[0]);
        float2 m1 = unpack2(macc[1]);
        int w = wid*4;
        if (w   < VV) mp[lane*VV + w]   = m0.x;
        if (w+1 < VV) mp[lane*VV + w+1] = m0.y;
        if (w+2 < VV) mp[lane*VV + w+2] = m1.x;
        if (w+3 < VV) mp[lane*VV + w+3] = m1.y;
    }
}

// ---------------------------------------------------------------------------
// kA2: reduce partials, A_adp = A + tanh(M/(IC*T)) * alpha
// ---------------------------------------------------------------------------
__global__ void kA2(const float* __restrict__ A, const float* __restrict__ alpha)
{
    int idx = blockIdx.x * 256 + threadIdx.x;
    if (idx >= NN*SS*VV*VV) return;
    float m = 0.f;
    #pragma unroll
    for (int ch = 0; ch < NCH; ch++)
        m += g_Mpart[ch*(NN*SS*VV*VV) + idx];
    g_Aadp[idx] = A[idx % (SS*VV*VV)]
                + tanhf(m * (1.f/(float)(ICn*TD))) * alpha[0];
}

// ---------------------------------------------------------------------------
// Kernel B (round-4 version): per (t-tile, n): for each s:
// xm = x_tile @ A_adp (K=25), y += WdT @ xm (K=64, o-pair FMA2).
// ---------------------------------------------------------------------------
__global__ __launch_bounds__(256) void kB(
    const float* __restrict__ x,
    const float* __restrict__ wd, const float* __restrict__ db,
    const float* __restrict__ bng, const float* __restrict__ bnb,
    const float* __restrict__ bnm, const float* __restrict__ bnv,
    float* __restrict__ out)
{
    extern __shared__ float sm[];
    float* s_x     = sm;                    // CC*5*XROW = 8960
    float* s_xm    = s_x   + CC*5*XROW;     // CC*XMS    = 8448
    float* s_wdT   = s_xm  + CC*XMS;        // CC*68     = 4352
    float* s_Aad   = s_wdT + CC*68;         // 28*32     = 896
    float* s_scale = s_Aad + 28*32;         // 64
    float* s_off   = s_scale + 64;          // 64

    const int tid  = threadIdx.x;
    const int wid  = tid >> 5;
    const int lane = tid & 31;
    const int tb = blockIdx.x;
    const int n  = blockIdx.y;
    const int t0 = tb * TTB;

    const float* xb = x + (size_t)n*(CC*TD*VV) + (size_t)t0*VV;

    for (int idx = tid; idx < CC*COLB; idx += 256) {
        int c = idx / COLB, col = idx % COLB;
        int lt = col / 25, v = col - lt*25;
        s_x[(c*5 + lt)*XROW + v] = xb[(size_t)c*(TD*VV) + col];
    }
    for (int idx = tid; idx < CC*5*3; idx += 256) {
        int row = idx / 3, p = idx % 3;
        s_x[row*XROW + 25 + p] = 0.f;
    }
    for (int idx = tid; idx < CC*XMS; idx += 256) s_xm[idx] = 0.f;
    if (tid < OCn) {
        float sc = bng[tid] * rsqrtf(bnv[tid] + EPSF);
        float ds = db[tid] + db[OCn + tid] + db[2*OCn + tid];
        s_scale[tid] = sc;
        s_off[tid]   = (ds - bnm[tid]) * sc + bnb[tid];
    }

    u64 yacc[4][4];
    #pragma unroll
    for (int p = 0; p < 4; p++)
        #pragma unroll
        for (int j = 0; j < 4; j++) yacc[p][j] = 0ull;

    for (int s = 0; s < SS; s++) {
        __syncthreads();
        for (int idx = tid; idx < 28*32; idx += 256) {
            int v = idx >> 5, w = idx & 31;
            s_Aad[idx] = (v < VV && w < VV)
                       ? g_Aadp[((size_t)n*SS + s)*(VV*VV) + v*VV + w] : 0.f;
        }
        for (int idx = tid; idx < CC*OCn; idx += 256) {
            int o = idx >> 6, c = idx & 63;
            s_wdT[c*68 + o] = wd[s*(OCn*CC) + idx];
        }
        __syncthreads();

        for (int lt = 0; lt < TTB; lt++) {
            u64 a0[2] = {0ull, 0ull};
            u64 a1[2] = {0ull, 0ull};
            const float* xp0 = &s_x[(lane*5 + lt)*XROW];
            const float* xp1 = &s_x[((lane+32)*5 + lt)*XROW];
            #pragma unroll
            for (int v4 = 0; v4 < 7; v4++) {
                float4 x0 = *reinterpret_cast<const float4*>(xp0 + v4*4);
                float4 x1 = *reinterpret_cast<const float4*>(xp1 + v4*4);
                #pragma unroll
                for (int vv = 0; vv < 4; vv++) {
                    ulonglong2 aa = *reinterpret_cast<const ulonglong2*>(
                        &s_Aad[(v4*4+vv)*32 + wid*4]);
                    float xs0 = (&x0.x)[vv], xs1 = (&x1.x)[vv];
                    u64 xd0 = pack2(xs0, xs0);
                    u64 xd1 = pack2(xs1, xs1);
                    fma2(a0[0], xd0, aa.x);
                    fma2(a0[1], xd0, aa.y);
                    fma2(a1[0], xd1, aa.x);
                    fma2(a1[1], xd1, aa.y);
                }
            }
            float2 p00 = unpack2(a0[0]), p01 = unpack2(a0[1]);
            float2 p10 = unpack2(a1[0]), p11 = unpack2(a1[1]);
            int w = wid*4;
            if (w < VV) {
                s_xm[lane*XMS      + lt*25 + w] = p00.x;
                s_xm[(lane+32)*XMS + lt*25 + w] = p10.x;
            }
            if (w+1 < VV) {
                s_xm[lane*XMS      + lt*25 + w+1] = p00.y;
                s_xm[(lane+32)*XMS + lt*25 + w+1] = p10.y;
            }
            if (w+2 < VV) {
                s_xm[lane*XMS      + lt*25 + w+2] = p01.x;
                s_xm[(lane+32)*XMS + lt*25 + w+2] = p11.x;
            }
            if (w+3 < VV) {
                s_xm[lane*XMS      + lt*25 + w+3] = p01.y;
                s_xm[(lane+32)*XMS + lt*25 + w+3] = p11.y;
            }
        }
        __syncthreads();

        #pragma unroll 4
        for (int c = 0; c < CC; c++) {
            float4 xmv = *reinterpret_cast<const float4*>(&s_xm[c*XMS + lane*4]);
            u64 xd0 = pack2(xmv.x, xmv.x);
            u64 xd1 = pack2(xmv.y, xmv.y);
            u64 xd2 = pack2(xmv.z, xmv.z);
            u64 xd3 = pack2(xmv.w, xmv.w);
            ulonglong2 w01 = *reinterpret_cast<const ulonglong2*>(
                &s_wdT[c*68 + wid*8]);
            ulonglong2 w23 = *reinterpret_cast<const ulonglong2*>(
                &s_wdT[c*68 + wid*8 + 4]);
            fma2(yacc[0][0], w01.x, xd0); fma2(yacc[0][1], w01.x, xd1);
            fma2(yacc[0][2], w01.x, xd2); fma2(yacc[0][3], w01.x, xd3);
            fma2(yacc[1][0], w01.y, xd0); fma2(yacc[1][1], w01.y, xd1);
            fma2(yacc[1][2], w01.y, xd2); fma2(yacc[1][3], w01.y, xd3);
            fma2(yacc[2][0], w23.x, xd0); fma2(yacc[2][1], w23.x, xd1);
            fma2(yacc[2][2], w23.x, xd2); fma2(yacc[2][3], w23.x, xd3);
            fma2(yacc[3][0], w23.y, xd0); fma2(yacc[3][1], w23.y, xd1);
            fma2(yacc[3][2], w23.y, xd2); fma2(yacc[3][3], w23.y, xd3);
        }
    }

    float* ob = out + (size_t)n*(CC*TD*VV) + (size_t)t0*VV;
    #pragma unroll
    for (int p = 0; p < 4; p++) {
        int oe = wid*8 + 2*p, oo = oe + 1;
        float sce = s_scale[oe], ofe = s_off[oe];
        float sco = s_scale[oo], ofo = s_off[oo];
        #pragma unroll
        for (int j = 0; j < 4; j++) {
            int col = lane*4 + j;
            if (col < COLB) {
                int lt = col / 25, v = col - lt*25;
                float2 y2 = unpack2(yacc[p][j]);
                float ve = y2.x*sce + ofe + s_x[(oe*5 + lt)*XROW + v];
                float vo = y2.y*sco + ofo + s_x[(oo*5 + lt)*XROW + v];
                ob[(size_t)oe*(TD*VV) + col] = fmaxf(ve, 0.f);
                ob[(size_t)oo*(TD*VV) + col] = fmaxf(vo, 0.f);
            }
        }
    }
}

// ---------------------------------------------------------------------------
extern "C" void kernel_launch(void* const* d_in, const int* in_sizes, int n_in,
                              void* d_out, int out_size)
{
    const float* x     = (const float*)d_in[0];
    const float* A     = (const float*)d_in[1];
    const float* alpha = (const float*)d_in[2];
    const float* caw   = (const float*)d_in[3];
    const float* cab   = (const float*)d_in[4];
    const float* cbw   = (const float*)d_in[5];
    const float* cbb   = (const float*)d_in[6];
    const float* bag   = (const float*)d_in[7];
    const float* babt  = (const float*)d_in[8];
    const float* bam   = (const float*)d_in[9];
    const float* bav   = (const float*)d_in[10];
    const float* bbg   = (const float*)d_in[11];
    const float* bbbt  = (const float*)d_in[12];
    const float* bbm   = (const float*)d_in[13];
    const float* bbv   = (const float*)d_in[14];
    const float* cdw   = (const float*)d_in[15];
    const float* cdb   = (const float*)d_in[16];
    const float* bng   = (const float*)d_in[17];
    const float* bnb   = (const float*)d_in[18];
    const float* bnm   = (const float*)d_in[19];
    const float* bnv   = (const float*)d_in[20];
    float* out = (float*)d_out;

    const int smemB = (CC*5*XROW + CC*XMS + CC*68 + 28*32 + 64 + 64) * sizeof(float);
    cudaFuncSetAttribute(kB, cudaFuncAttributeMaxDynamicSharedMemorySize, smemB);

    kConv<<<dim3(NTCB, SS, NN), 256>>>(x, caw, cab, cbw, cbb,
                                       bag, babt, bam, bav,
                                       bbg, bbbt, bbm, bbv);
    kM<<<dim3(NCH, SS, NN), 256>>>();
    kA2<<<(NN*SS*VV*VV + 255)/256, 256>>>(A, alpha);
    kB<<<dim3(NTB, NN), 256, smemB>>>(x, cdw, cdb, bng, bnb, bnm, bnv, out);
}

// round 6
// speedup vs baseline: 1.2935x; 1.0130x over previous
#include <cuda_runtime.h>
#include <cuda_bf16.h>

#define EPSF 1e-5f

// Problem dims
#define NN  64
#define CC  64
#define TD  300
#define VV  25
#define SS  3
#define ICn 16
#define OCn 64

// kConv tiling
#define TCB   20              // t's per block
#define NTCB  (TD/TCB)        // 15
#define COLSB (TCB*VV)        // 500 columns per block

// kM tiling
#define NCH  5
#define KTOT (ICn*TD)         // 4800 rows per (n,s)
#define KCH  (KTOT/NCH)       // 960 rows per chunk
#define KST  64               // rows per stage
#define NSTG (KCH/KST)        // 15

// kB tiling
#define TTB  5
#define COLB (TTB*VV)         // 125
#define XMS  132
#define NTB  (TD/TTB)         // 60
#define XROW 28

typedef unsigned long long u64;

// a,b interleaved as bf16 pairs: g_ab[(n*S+s)*4800 + t*16 + i][v(pad 32)] = (a, b)
__device__ __nv_bfloat162 g_ab[(size_t)NN*SS*KTOT*32];
__device__ float g_Mpart[NCH*NN*SS*VV*VV];
__device__ float g_Aadp [NN*SS*VV*VV];

__device__ __forceinline__ float tanh_fast(float x) {
    float y;
    asm("tanh.approx.f32 %0, %1;" : "=f"(y) : "f"(x));
    return y;
}
__device__ __forceinline__ u64 pack2(float lo, float hi) {
    u64 r; asm("mov.b64 %0, {%1, %2};" : "=l"(r) : "f"(lo), "f"(hi)); return r;
}
__device__ __forceinline__ float2 unpack2(u64 p) {
    float2 r; asm("mov.b64 {%0, %1}, %2;" : "=f"(r.x), "=f"(r.y) : "l"(p)); return r;
}
__device__ __forceinline__ void fma2(u64& d, u64 a, u64 b) {
    asm("fma.rn.f32x2 %0, %1, %2, %0;" : "+l"(d) : "l"(a), "l"(b));
}

// ---------------------------------------------------------------------------
// kConv: a = tanh(bn(Wa x)), b = tanh(bn(Wb x)) -> g_ab (bf16 pairs).
// Streaming, no barriers in main loop. Thread = 2 cols x all 16 i's.
// ---------------------------------------------------------------------------
__global__ __launch_bounds__(256) void kConv(
    const float* __restrict__ x,
    const float* __restrict__ wa, const float* __restrict__ ba,
    const float* __restrict__ wb, const float* __restrict__ bb,
    const float* __restrict__ gag, const float* __restrict__ gab,
    const float* __restrict__ gam, const float* __restrict__ gav,
    const float* __restrict__ gbg, const float* __restrict__ gbb,
    const float* __restrict__ gbm, const float* __restrict__ gbv)
{
    __shared__ __align__(16) float s_w[CC*32];   // [c][0..15]=wa', [16..31]=wb'
    __shared__ float s_sha[ICn], s_shb[ICn];

    const int tid = threadIdx.x;
    const int tc  = blockIdx.x;
    const int s   = blockIdx.y;
    const int n   = blockIdx.z;

    for (int idx = tid; idx < ICn*CC; idx += 256) {
        int i = idx / CC, c = idx % CC;
        float sca = gag[s*ICn+i] * rsqrtf(gav[s*ICn+i] + EPSF);
        float scb = gbg[s*ICn+i] * rsqrtf(gbv[s*ICn+i] + EPSF);
        s_w[c*32 + i]      = wa[s*ICn*CC + idx] * sca;
        s_w[c*32 + 16 + i] = wb[s*ICn*CC + idx] * scb;
    }
    if (tid < ICn) {
        float sca = gag[s*ICn+tid] * rsqrtf(gav[s*ICn+tid] + EPSF);
        float scb = gbg[s*ICn+tid] * rsqrtf(gbv[s*ICn+tid] + EPSF);
        s_sha[tid] = (ba[s*ICn+tid] - gam[s*ICn+tid]) * sca + gab[s*ICn+tid];
        s_shb[tid] = (bb[s*ICn+tid] - gbm[s*ICn+tid]) * scb + gbb[s*ICn+tid];
    }
    __syncthreads();
    if (tid >= COLSB/2) return;          // 250 active; no barriers after this

    const int col0 = tc*COLSB + 2*tid;
    const int col1 = col0 + 1;
    const int t0 = col0 / 25, v0 = col0 - 25*t0;
    const int t1 = col1 / 25, v1 = col1 - 25*t1;

    u64 accA0[8], accA1[8], accB0[8], accB1[8];
    #pragma unroll
    for (int p = 0; p < 8; p++) {
        u64 ia = pack2(s_sha[2*p], s_sha[2*p+1]);
        u64 ib = pack2(s_shb[2*p], s_shb[2*p+1]);
        accA0[p] = ia; accA1[p] = ia;
        accB0[p] = ib; accB1[p] = ib;
    }

    const float* xp = x + (size_t)n*(CC*TD*VV) + col0;
    #pragma unroll 4
    for (int c = 0; c < CC; c++) {
        float2 xv = *reinterpret_cast<const float2*>(xp + (size_t)c*(TD*VV));
        u64 xd0 = pack2(xv.x, xv.x);
        u64 xd1 = pack2(xv.y, xv.y);
        const ulonglong2* wrow = reinterpret_cast<const ulonglong2*>(&s_w[c*32]);
        #pragma unroll
        for (int g = 0; g < 4; g++) {
            ulonglong2 w2 = wrow[g];
            fma2(accA0[2*g],   w2.x, xd0); fma2(accA1[2*g],   w2.x, xd1);
            fma2(accA0[2*g+1], w2.y, xd0); fma2(accA1[2*g+1], w2.y, xd1);
        }
        #pragma unroll
        for (int g = 0; g < 4; g++) {
            ulonglong2 w2 = wrow[4+g];
            fma2(accB0[2*g],   w2.x, xd0); fma2(accB1[2*g],   w2.x, xd1);
            fma2(accB0[2*g+1], w2.y, xd0); fma2(accB1[2*g+1], w2.y, xd1);
        }
    }

    __nv_bfloat162* gb = g_ab + (size_t)(n*SS + s)*KTOT*32;
    #pragma unroll
    for (int p = 0; p < 8; p++) {
        float2 a0 = unpack2(accA0[p]);
        float2 b0 = unpack2(accB0[p]);
        float2 a1 = unpack2(accA1[p]);
        float2 b1 = unpack2(accB1[p]);
        __nv_bfloat162 h;
        h.x = __float2bfloat16(tanh_fast(a0.x));
        h.y = __float2bfloat16(tanh_fast(b0.x));
        gb[(size_t)(t0*ICn + 2*p)*32 + v0] = h;
        h.x = __float2bfloat16(tanh_fast(a0.y));
        h.y = __float2bfloat16(tanh_fast(b0.y));
        gb[(size_t)(t0*ICn + 2*p+1)*32 + v0] = h;
        h.x = __float2bfloat16(tanh_fast(a1.x));
        h.y = __float2bfloat16(tanh_fast(b1.x));
        gb[(size_t)(t1*ICn + 2*p)*32 + v1] = h;
        h.x = __float2bfloat16(tanh_fast(a1.y));
        h.y = __float2bfloat16(tanh_fast(b1.y));
        gb[(size_t)(t1*ICn + 2*p+1)*32 + v1] = h;
    }
}

// ---------------------------------------------------------------------------
// kM: partial M[v,w] = sum_k a[k,v]*b[k,w] over this chunk's 960 rows.
// ---------------------------------------------------------------------------
__global__ __launch_bounds__(256) void kM()
{
    __shared__ __align__(16) float s_a32[KST*32];
    __shared__ __align__(16) float s_b32[KST*32];

    const int tid  = threadIdx.x;
    const int wid  = tid >> 5;
    const int lane = tid & 31;
    const int chunk = blockIdx.x;
    const int s     = blockIdx.y;
    const int n     = blockIdx.z;

    const uint4* gsrc = reinterpret_cast<const uint4*>(
        g_ab + ((size_t)(n*SS + s)*KTOT + (size_t)chunk*KCH)*32);

    u64 macc[2] = {0ull, 0ull};

    for (int st = 0; st < NSTG; st++) {
        __syncthreads();
        #pragma unroll
        for (int rep = 0; rep < 2; rep++) {
            int u = tid + rep*256;
            uint4 val = gsrc[st*512 + u];
            int row = u >> 3, q = u & 7;
            float* pa = &s_a32[row*32 + q*4];
            float* pb = &s_b32[row*32 + q*4];
            float2 f0 = __bfloat1622float2(*reinterpret_cast<__nv_bfloat162*>(&val.x));
            float2 f1 = __bfloat1622float2(*reinterpret_cast<__nv_bfloat162*>(&val.y));
            float2 f2 = __bfloat1622float2(*reinterpret_cast<__nv_bfloat162*>(&val.z));
            float2 f3 = __bfloat1622float2(*reinterpret_cast<__nv_bfloat162*>(&val.w));
            pa[0] = f0.x; pb[0] = f0.y;
            pa[1] = f1.x; pb[1] = f1.y;
            pa[2] = f2.x; pb[2] = f2.y;
            pa[3] = f3.x; pb[3] = f3.y;
        }
        __syncthreads();
        #pragma unroll 8
        for (int kk = 0; kk < KST; kk++) {
            float av = s_a32[kk*32 + lane];
            u64 ap = pack2(av, av);
            ulonglong2 bv = *reinterpret_cast<const ulonglong2*>(
                &s_b32[kk*32 + wid*4]);
            fma2(macc[0], ap, bv.x);
            fma2(macc[1], ap, bv.y);
        }
    }

    if (lane < VV) {
        float* mp = &g_Mpart[((size_t)chunk*NN*SS + (size_t)n*SS + s)*(VV*VV)];
        float2 m0 = unpack2(macc[0]);
        float2 m1 = unpack2(macc[1]);
        int w = wid*4;
        if (w   < VV) mp[lane*VV + w]   = m0.x;
        if (w+1 < VV) mp[lane*VV + w+1] = m0.y;
        if (w+2 < VV) mp[lane*VV + w+2] = m1.x;
        if (w+3 < VV) mp[lane*VV + w+3] = m1.y;
    }
}

// ---------------------------------------------------------------------------
// kA2: reduce partials, A_adp = A + tanh(M/(IC*T)) * alpha
// ---------------------------------------------------------------------------
__global__ void kA2(const float* __restrict__ A, const float* __restrict__ alpha)
{
    int idx = blockIdx.x * 256 + threadIdx.x;
    if (idx >= NN*SS*VV*VV) return;
    float m = 0.f;
    #pragma unroll
    for (int ch = 0; ch < NCH; ch++)
        m += g_Mpart[ch*(NN*SS*VV*VV) + idx];
    g_Aadp[idx] = A[idx % (SS*VV*VV)]
                + tanhf(m * (1.f/(float)(ICn*TD))) * alpha[0];
}

// ---------------------------------------------------------------------------
// Kernel B: per (t-tile, n): for each s: xm = x_tile @ A_adp (K=25),
// y += WdT @ xm (K=64, o-pair FMA2). A_adp hoisted for all s; deep unroll.
// ---------------------------------------------------------------------------
__global__ __launch_bounds__(256) void kB(
    const float* __restrict__ x,
    const float* __restrict__ wd, const float* __restrict__ db,
    const float* __restrict__ bng, const float* __restrict__ bnb,
    const float* __restrict__ bnm, const float* __restrict__ bnv,
    float* __restrict__ out)
{
    extern __shared__ float sm[];
    float* s_x     = sm;                    // CC*5*XROW = 8960
    float* s_xm    = s_x   + CC*5*XROW;     // CC*XMS    = 8448
    float* s_wdT   = s_xm  + CC*XMS;        // CC*68     = 4352
    float* s_Aad   = s_wdT + CC*68;         // 3*28*32   = 2688 (all s)
    float* s_scale = s_Aad + 3*28*32;       // 64
    float* s_off   = s_scale + 64;          // 64

    const int tid  = threadIdx.x;
    const int wid  = tid >> 5;
    const int lane = tid & 31;
    const int tb = blockIdx.x;
    const int n  = blockIdx.y;
    const int t0 = tb * TTB;

    const float* xb = x + (size_t)n*(CC*TD*VV) + (size_t)t0*VV;

    for (int idx = tid; idx < CC*COLB; idx += 256) {
        int c = idx / COLB, col = idx % COLB;
        int lt = col / 25, v = col - lt*25;
        s_x[(c*5 + lt)*XROW + v] = xb[(size_t)c*(TD*VV) + col];
    }
    for (int idx = tid; idx < CC*5*3; idx += 256) {
        int row = idx / 3, p = idx % 3;
        s_x[row*XROW + 25 + p] = 0.f;
    }
    for (int idx = tid; idx < CC*XMS; idx += 256) s_xm[idx] = 0.f;
    // A_adp padded [3][28][32], zeros outside 25x25 — hoisted for all s
    for (int idx = tid; idx < 3*28*32; idx += 256) {
        int s  = idx / (28*32);
        int r  = idx - s*28*32;
        int v  = r >> 5, w = r & 31;
        s_Aad[idx] = (v < VV && w < VV)
                   ? g_Aadp[((size_t)n*SS + s)*(VV*VV) + v*VV + w] : 0.f;
    }
    if (tid < OCn) {
        float sc = bng[tid] * rsqrtf(bnv[tid] + EPSF);
        float ds = db[tid] + db[OCn + tid] + db[2*OCn + tid];
        s_scale[tid] = sc;
        s_off[tid]   = (ds - bnm[tid]) * sc + bnb[tid];
    }

    u64 yacc[4][4];
    #pragma unroll
    for (int p = 0; p < 4; p++)
        #pragma unroll
        for (int j = 0; j < 4; j++) yacc[p][j] = 0ull;

    for (int s = 0; s < SS; s++) {
        __syncthreads();   // xm safe to overwrite; wdT safe to reload
        for (int idx = tid; idx < CC*OCn; idx += 256) {
            int o = idx >> 6, c = idx & 63;
            s_wdT[c*68 + o] = wd[s*(OCn*CC) + idx];
        }
        __syncthreads();

        // GEMM1: xm[c][lt*25+w] = sum_v x[c][lt][v]*Aad[s][v][w]
        const float* Aad_s = &s_Aad[s*28*32];
        #pragma unroll 2
        for (int lt = 0; lt < TTB; lt++) {
            u64 a0[2] = {0ull, 0ull};
            u64 a1[2] = {0ull, 0ull};
            const float* xp0 = &s_x[(lane*5 + lt)*XROW];
            const float* xp1 = &s_x[((lane+32)*5 + lt)*XROW];
            #pragma unroll
            for (int v4 = 0; v4 < 7; v4++) {
                float4 x0 = *reinterpret_cast<const float4*>(xp0 + v4*4);
                float4 x1 = *reinterpret_cast<const float4*>(xp1 + v4*4);
                #pragma unroll
                for (int vv = 0; vv < 4; vv++) {
                    ulonglong2 aa = *reinterpret_cast<const ulonglong2*>(
                        &Aad_s[(v4*4+vv)*32 + wid*4]);
                    float xs0 = (&x0.x)[vv], xs1 = (&x1.x)[vv];
                    u64 xd0 = pack2(xs0, xs0);
                    u64 xd1 = pack2(xs1, xs1);
                    fma2(a0[0], xd0, aa.x);
                    fma2(a0[1], xd0, aa.y);
                    fma2(a1[0], xd1, aa.x);
                    fma2(a1[1], xd1, aa.y);
                }
            }
            float2 p00 = unpack2(a0[0]), p01 = unpack2(a0[1]);
            float2 p10 = unpack2(a1[0]), p11 = unpack2(a1[1]);
            int w = wid*4;
            if (w < VV) {
                s_xm[lane*XMS      + lt*25 + w] = p00.x;
                s_xm[(lane+32)*XMS + lt*25 + w] = p10.x;
            }
            if (w+1 < VV) {
                s_xm[lane*XMS      + lt*25 + w+1] = p00.y;
                s_xm[(lane+32)*XMS + lt*25 + w+1] = p10.y;
            }
            if (w+2 < VV) {
                s_xm[lane*XMS      + lt*25 + w+2] = p01.x;
                s_xm[(lane+32)*XMS + lt*25 + w+2] = p11.x;
            }
            if (w+3 < VV) {
                s_xm[lane*XMS      + lt*25 + w+3] = p01.y;
                s_xm[(lane+32)*XMS + lt*25 + w+3] = p11.y;
            }
        }
        __syncthreads();

        // GEMM2: y[o][col] += wdT[c][o]*xm[c][col]; deep unroll for ILP
        #pragma unroll 8
        for (int c = 0; c < CC; c++) {
            float4 xmv = *reinterpret_cast<const float4*>(&s_xm[c*XMS + lane*4]);
            u64 xd0 = pack2(xmv.x, xmv.x);
            u64 xd1 = pack2(xmv.y, xmv.y);
            u64 xd2 = pack2(xmv.z, xmv.z);
            u64 xd3 = pack2(xmv.w, xmv.w);
            ulonglong2 w01 = *reinterpret_cast<const ulonglong2*>(
                &s_wdT[c*68 + wid*8]);
            ulonglong2 w23 = *reinterpret_cast<const ulonglong2*>(
                &s_wdT[c*68 + wid*8 + 4]);
            fma2(yacc[0][0], w01.x, xd0); fma2(yacc[0][1], w01.x, xd1);
            fma2(yacc[0][2], w01.x, xd2); fma2(yacc[0][3], w01.x, xd3);
            fma2(yacc[1][0], w01.y, xd0); fma2(yacc[1][1], w01.y, xd1);
            fma2(yacc[1][2], w01.y, xd2); fma2(yacc[1][3], w01.y, xd3);
            fma2(yacc[2][0], w23.x, xd0); fma2(yacc[2][1], w23.x, xd1);
            fma2(yacc[2][2], w23.x, xd2); fma2(yacc[2][3], w23.x, xd3);
            fma2(yacc[3][0], w23.y, xd0); fma2(yacc[3][1], w23.y, xd1);
            fma2(yacc[3][2], w23.y, xd2); fma2(yacc[3][3], w23.y, xd3);
        }
    }

    float* ob = out + (size_t)n*(CC*TD*VV) + (size_t)t0*VV;
    #pragma unroll
    for (int p = 0; p < 4; p++) {
        int oe = wid*8 + 2*p, oo = oe + 1;
        float sce = s_scale[oe], ofe = s_off[oe];
        float sco = s_scale[oo], ofo = s_off[oo];
        #pragma unroll
        for (int j = 0; j < 4; j++) {
            int col = lane*4 + j;
            if (col < COLB) {
                int lt = col / 25, v = col - lt*25;
                float2 y2 = unpack2(yacc[p][j]);
                float ve = y2.x*sce + ofe + s_x[(oe*5 + lt)*XROW + v];
                float vo = y2.y*sco + ofo + s_x[(oo*5 + lt)*XROW + v];
                ob[(size_t)oe*(TD*VV) + col] = fmaxf(ve, 0.f);
                ob[(size_t)oo*(TD*VV) + col] = fmaxf(vo, 0.f);
            }
        }
    }
}

// ---------------------------------------------------------------------------
extern "C" void kernel_launch(void* const* d_in, const int* in_sizes, int n_in,
                              void* d_out, int out_size)
{
    const float* x     = (const float*)d_in[0];
    const float* A     = (const float*)d_in[1];
    const float* alpha = (const float*)d_in[2];
    const float* caw   = (const float*)d_in[3];
    const float* cab   = (const float*)d_in[4];
    const float* cbw   = (const float*)d_in[5];
    const float* cbb   = (const float*)d_in[6];
    const float* bag   = (const float*)d_in[7];
    const float* babt  = (const float*)d_in[8];
    const float* bam   = (const float*)d_in[9];
    const float* bav   = (const float*)d_in[10];
    const float* bbg   = (const float*)d_in[11];
    const float* bbbt  = (const float*)d_in[12];
    const float* bbm   = (const float*)d_in[13];
    const float* bbv   = (const float*)d_in[14];
    const float* cdw   = (const float*)d_in[15];
    const float* cdb   = (const float*)d_in[16];
    const float* bng   = (const float*)d_in[17];
    const float* bnb   = (const float*)d_in[18];
    const float* bnm   = (const float*)d_in[19];
    const float* bnv   = (const float*)d_in[20];
    float* out = (float*)d_out;

    const int smemB = (CC*5*XROW + CC*XMS + CC*68 + 3*28*32 + 64 + 64) * sizeof(float);
    cudaFuncSetAttribute(kB, cudaFuncAttributeMaxDynamicSharedMemorySize, smemB);

    kConv<<<dim3(NTCB, SS, NN), 256>>>(x, caw, cab, cbw, cbb,
                                       bag, babt, bam, bav,
                                       bbg, bbbt, bbm, bbv);
    kM<<<dim3(NCH, SS, NN), 256>>>();
    kA2<<<(NN*SS*VV*VV + 255)/256, 256>>>(A, alpha);
    kB<<<dim3(NTB, NN), 256, smemB>>>(x, cdw, cdb, bng, bnb, bnm, bnv, out);
}